// round 1
// baseline (speedup 1.0000x reference)
#include <cuda_runtime.h>
#include <cuda_bf16.h>
#include <cstdint>
#include <cstddef>

// Problem constants (fixed shapes per reference)
#define NROWS 4096      // batch N
#define INF   4096      // input features
#define OUTF  4096      // output features
#define KDIM  8192      // virtual K = 2 * INF (hi + lo split)

// GEMM tiling
#define BM 128
#define BN 128
#define BK 32
#define STAGES 3
#define LDS 40                       // padded smem row stride in bf16 (80 B)
#define STAGE_BYTES (BM * LDS * 2)   // 10240 B per tile per stage
#define KT (KDIM / BK)               // 256 k-tiles

// Persistent scratch (allowed: __device__ globals, no allocation)
__device__ __nv_bfloat16 g_xs[(size_t)NROWS * KDIM];   // [n][k] k<4096: hi, k>=4096: lo (64 MB)
__device__ __nv_bfloat16 g_q[(size_t)OUTF * INF];      // (q - 8) exact in bf16 (32 MB)

// ---------------------------------------------------------------------------
// Prep 1: split x (fp32) into hi/lo bf16, laid out [n][8192]
// ---------------------------------------------------------------------------
__global__ void split_x_kernel(const float* __restrict__ x) {
    int idx = blockIdx.x * blockDim.x + threadIdx.x;   // one thread per 4 floats
    // total = 4096*4096/4 = 4194304 threads
    int n  = idx >> 10;            // 1024 quads per row
    int k4 = (idx & 1023) << 2;
    float4 v = reinterpret_cast<const float4*>(x)[idx];

    __nv_bfloat16 h0 = __float2bfloat16(v.x);
    __nv_bfloat16 h1 = __float2bfloat16(v.y);
    __nv_bfloat16 h2 = __float2bfloat16(v.z);
    __nv_bfloat16 h3 = __float2bfloat16(v.w);
    __nv_bfloat16 l0 = __float2bfloat16(v.x - __bfloat162float(h0));
    __nv_bfloat16 l1 = __float2bfloat16(v.y - __bfloat162float(h1));
    __nv_bfloat16 l2 = __float2bfloat16(v.z - __bfloat162float(h2));
    __nv_bfloat16 l3 = __float2bfloat16(v.w - __bfloat162float(h3));

    __nv_bfloat16* hi = &g_xs[(size_t)n * KDIM + k4];
    __nv_bfloat16* lo = &g_xs[(size_t)n * KDIM + INF + k4];
    reinterpret_cast<__nv_bfloat162*>(hi)[0] = __nv_bfloat162{h0, h1};
    reinterpret_cast<__nv_bfloat162*>(hi)[1] = __nv_bfloat162{h2, h3};
    reinterpret_cast<__nv_bfloat162*>(lo)[0] = __nv_bfloat162{l0, l1};
    reinterpret_cast<__nv_bfloat162*>(lo)[1] = __nv_bfloat162{l2, l3};
}

// ---------------------------------------------------------------------------
// Prep 2: unpack int4 nibbles -> bf16 (q - 8), row-major [o][4096]
// low nibble -> even k, high nibble -> odd k
// ---------------------------------------------------------------------------
__global__ void unpack_w_kernel(const int* __restrict__ wp) {
    int idx = blockIdx.x * blockDim.x + threadIdx.x;   // one thread per 4 packed words
    // total = 4096*2048/4 = 2097152 threads
    int4 w = reinterpret_cast<const int4*>(wp)[idx];
    __nv_bfloat16 out[8];
    int vals[4] = {w.x, w.y, w.z, w.w};
#pragma unroll
    for (int j = 0; j < 4; ++j) {
        int lo = (vals[j] & 0xF) - 8;
        int hi = ((vals[j] >> 4) & 0xF) - 8;
        out[2 * j]     = __float2bfloat16((float)lo);
        out[2 * j + 1] = __float2bfloat16((float)hi);
    }
    reinterpret_cast<uint4*>(&g_q[(size_t)idx * 8])[0] = *reinterpret_cast<uint4*>(out);
}

// ---------------------------------------------------------------------------
// GEMM: C[n,o] = sum_k A'[n,k] * B'[o,k], then out = scale[o]*C + bias[o]
// A' = g_xs (K=8192), B'[o,k] = g_q[o][k & 4095]
// ---------------------------------------------------------------------------
#define CP_ASYNC16(dst, src) \
    asm volatile("cp.async.cg.shared.global [%0], [%1], 16;\n" :: "r"(dst), "l"(src))
#define CP_COMMIT() asm volatile("cp.async.commit_group;\n" ::)
#define CP_WAIT(n)  asm volatile("cp.async.wait_group %0;\n" :: "n"(n))

__device__ __forceinline__ void ldmatrix_x4(uint32_t* r, uint32_t addr) {
    asm volatile("ldmatrix.sync.aligned.m8n8.x4.shared.b16 {%0,%1,%2,%3}, [%4];\n"
                 : "=r"(r[0]), "=r"(r[1]), "=r"(r[2]), "=r"(r[3]) : "r"(addr));
}
__device__ __forceinline__ void ldmatrix_x2(uint32_t* r, uint32_t addr) {
    asm volatile("ldmatrix.sync.aligned.m8n8.x2.shared.b16 {%0,%1}, [%2];\n"
                 : "=r"(r[0]), "=r"(r[1]) : "r"(addr));
}
__device__ __forceinline__ void mma_bf16(float* d, const uint32_t* a, const uint32_t* b) {
    asm volatile("mma.sync.aligned.m16n8k16.row.col.f32.bf16.bf16.f32 "
                 "{%0,%1,%2,%3}, {%4,%5,%6,%7}, {%8,%9}, {%0,%1,%2,%3};\n"
                 : "+f"(d[0]), "+f"(d[1]), "+f"(d[2]), "+f"(d[3])
                 : "r"(a[0]), "r"(a[1]), "r"(a[2]), "r"(a[3]), "r"(b[0]), "r"(b[1]));
}

__device__ __forceinline__ void load_tile(int tid, int bm, int bn, int stage, int kt,
                                          uint32_t sA, uint32_t sB) {
    int k0 = kt * BK;
    int kb = k0 & (INF - 1);
#pragma unroll
    for (int i = 0; i < 2; ++i) {
        int chunk = tid + i * 256;
        int row = chunk >> 2;
        int c   = chunk & 3;
        const __nv_bfloat16* srcA = &g_xs[(size_t)(bm + row) * KDIM + k0 + c * 8];
        uint32_t dstA = sA + stage * STAGE_BYTES + (row * LDS + c * 8) * 2;
        CP_ASYNC16(dstA, srcA);
        const __nv_bfloat16* srcB = &g_q[(size_t)(bn + row) * INF + kb + c * 8];
        uint32_t dstB = sB + stage * STAGE_BYTES + (row * LDS + c * 8) * 2;
        CP_ASYNC16(dstB, srcB);
    }
}

__global__ void gemm_kernel(float* __restrict__ out,
                            const float* __restrict__ scales,
                            const float* __restrict__ bias) {
    extern __shared__ __nv_bfloat16 smem[];
    const int tid  = threadIdx.x;
    const int lane = tid & 31;
    const int warp = tid >> 5;
    const int wm   = warp & 1;    // 2 warps along M
    const int wn   = warp >> 1;   // 4 warps along N
    const int bm   = blockIdx.y * BM;
    const int bn   = blockIdx.x * BN;

    uint32_t sA = (uint32_t)__cvta_generic_to_shared(smem);
    uint32_t sB = sA + STAGES * STAGE_BYTES;

    float acc[4][4][4];
#pragma unroll
    for (int mi = 0; mi < 4; ++mi)
#pragma unroll
        for (int ni = 0; ni < 4; ++ni)
#pragma unroll
            for (int j = 0; j < 4; ++j) acc[mi][ni][j] = 0.0f;

    // Prologue: fill STAGES-1 stages
#pragma unroll
    for (int s = 0; s < STAGES - 1; ++s) {
        load_tile(tid, bm, bn, s, s, sA, sB);
        CP_COMMIT();
    }

    for (int kt = 0; kt < KT; ++kt) {
        CP_WAIT(STAGES - 2);
        __syncthreads();

        int ld_kt = kt + STAGES - 1;
        if (ld_kt < KT) load_tile(tid, bm, bn, ld_kt % STAGES, ld_kt, sA, sB);
        CP_COMMIT();

        int stage = kt % STAGES;
        uint32_t aBase = sA + stage * STAGE_BYTES;
        uint32_t bBase = sB + stage * STAGE_BYTES;

#pragma unroll
        for (int ks = 0; ks < BK; ks += 16) {
            uint32_t ra[4][4];
            uint32_t rb[4][2];
#pragma unroll
            for (int mi = 0; mi < 4; ++mi) {
                int r   = wm * 64 + mi * 16 + (lane & 15);
                int col = ks + ((lane >> 4) << 3);
                ldmatrix_x4(ra[mi], aBase + (r * LDS + col) * 2);
            }
#pragma unroll
            for (int ni = 0; ni < 4; ++ni) {
                int r   = wn * 32 + ni * 8 + (lane & 7);
                int col = ks + (((lane >> 3) & 1) << 3);
                ldmatrix_x2(rb[ni], bBase + (r * LDS + col) * 2);
            }
#pragma unroll
            for (int mi = 0; mi < 4; ++mi)
#pragma unroll
                for (int ni = 0; ni < 4; ++ni)
                    mma_bf16(acc[mi][ni], ra[mi], rb[ni]);
        }
        __syncthreads();
    }

    // Epilogue: out = scale[o]*acc + bias[o]
#pragma unroll
    for (int mi = 0; mi < 4; ++mi) {
#pragma unroll
        for (int ni = 0; ni < 4; ++ni) {
            int row = bm + wm * 64 + mi * 16 + (lane >> 2);
            int col = bn + wn * 32 + ni * 8 + (lane & 3) * 2;
            float s0 = scales[col], s1 = scales[col + 1];
            float b0 = bias[col],   b1 = bias[col + 1];
            float2 v0 = make_float2(acc[mi][ni][0] * s0 + b0,
                                    acc[mi][ni][1] * s1 + b1);
            float2 v1 = make_float2(acc[mi][ni][2] * s0 + b0,
                                    acc[mi][ni][3] * s1 + b1);
            *reinterpret_cast<float2*>(out + (size_t)row * OUTF + col) = v0;
            *reinterpret_cast<float2*>(out + (size_t)(row + 8) * OUTF + col) = v1;
        }
    }
}

// ---------------------------------------------------------------------------
// Launch
// ---------------------------------------------------------------------------
extern "C" void kernel_launch(void* const* d_in, const int* in_sizes, int n_in,
                              void* d_out, int out_size) {
    const float* x      = (const float*)d_in[0];
    const int*   wp     = (const int*)d_in[1];
    const float* scales = (const float*)d_in[2];
    const float* bias   = (const float*)d_in[3];
    float*       out    = (float*)d_out;

    (void)in_sizes; (void)n_in; (void)out_size;

    // Prep: split x into hi/lo bf16 and unpack int4 -> bf16 (q-8)
    split_x_kernel<<<(NROWS * INF / 4) / 256, 256>>>(x);
    unpack_w_kernel<<<(OUTF * (INF / 2) / 4) / 256, 256>>>(wp);

    // GEMM
    static bool attr_set = false;
    // NOTE: setting the attribute repeatedly is idempotent & capture-safe;
    // do it unconditionally to avoid any static-guard semantics.
    cudaFuncSetAttribute(gemm_kernel,
                         cudaFuncAttributeMaxDynamicSharedMemorySize,
                         STAGES * STAGE_BYTES * 2);
    (void)attr_set;
    dim3 grid(OUTF / BN, NROWS / BM);
    gemm_kernel<<<grid, 256, STAGES * STAGE_BYTES * 2>>>(out, scales, bias);
}